// round 1
// baseline (speedup 1.0000x reference)
#include <cuda_runtime.h>
#include <math.h>

#define B_ 64
#define T_ 1024
#define D_ 512
#define U_ 1024

// scratch (device globals — no allocation allowed)
__device__ float g_projh[B_ * U_];
__device__ float g_logits[B_ * T_];

// Blackwell packed fp32x2 FMA: 2 FMAs/instr -> full 128-lane fp32 rate
__device__ __forceinline__ unsigned long long f2fma(unsigned long long a,
                                                    unsigned long long b,
                                                    unsigned long long c) {
    unsigned long long d;
    asm("fma.rn.f32x2 %0, %1, %2, %3;" : "=l"(d) : "l"(a), "l"(b), "l"(c));
    return d;
}
__device__ __forceinline__ float2 unpack2(unsigned long long v) {
    float2 r;
    asm("mov.b64 {%0, %1}, %2;" : "=f"(r.x), "=f"(r.y) : "l"(v));
    return r;
}

// ---------------------------------------------------------------------------
// Kernel 1: proj_h[b,u] = hidden[b,:] @ W2[:,u] + W2_b[u]
// grid (B, U/128), 128 threads
// ---------------------------------------------------------------------------
__global__ void projh_kernel(const float* __restrict__ hidden,
                             const float* __restrict__ W2,
                             const float* __restrict__ W2b) {
    __shared__ __align__(16) float hs[D_];
    const int b = blockIdx.x;
    const int uc = blockIdx.y;
    const int tid = threadIdx.x;

    ((float4*)hs)[tid] = ((const float4*)(hidden + b * D_))[tid];
    __syncthreads();

    const int u = uc * 128 + tid;
    float acc = 0.f;
#pragma unroll 8
    for (int d = 0; d < D_; d++) acc += hs[d] * W2[d * U_ + u];
    g_projh[b * U_ + u] = acc + W2b[u];
}

// ---------------------------------------------------------------------------
// Kernel 2: fused  logits[b,t] = V_b + sum_u V[u]*tanh(f[b,t,:]@W1[:,u] + W1_b[u] + proj_h[b,u])
// Tile: M=128 tokens x N=128 units, K-chunks of 16. 256 threads, 8x8 micro-tile (f32x2 packed).
// grid: (B*T)/128 blocks
// ---------------------------------------------------------------------------
__global__ void __launch_bounds__(256, 2)
score_kernel(const float* __restrict__ feat, const float* __restrict__ W1,
             const float* __restrict__ W1b, const float* __restrict__ Vw,
             const float* __restrict__ Vb) {
    // A (features) stored DUPLICATED ({a,a} pairs, transposed): As2[k][2m],[2m+1]
    // row stride 260 floats: keeps LDS.128 16B-aligned and halves STS conflicts
    __shared__ __align__(16) float As2[16][260];
    __shared__ __align__(16) float Bs[16][128];   // W1 tile, plain [k][n]
    __shared__ float shV[128];
    __shared__ float shPh[128];
    __shared__ float red[128][17];

    const int tid = threadIdx.x;
    const int tx = tid & 15;        // column group
    const int ty = tid >> 4;        // row group
    const int bt0 = blockIdx.x * 128;
    const int b = bt0 >> 10;        // T_=1024
    const int r0 = ty * 8;          // token rows r0..r0+7
    const int c0 = tx * 8;          // unit cols  c0..c0+7

    float logit[8];
#pragma unroll
    for (int i = 0; i < 8; i++) logit[i] = 0.f;

    for (int nt = 0; nt < U_ / 128; nt++) {
        const int n0 = nt * 128;
        __syncthreads();  // previous epilogue done before shV/shPh rewrite
        if (tid < 128) {
            shV[tid] = Vw[n0 + tid];
            shPh[tid] = g_projh[b * U_ + n0 + tid] + W1b[n0 + tid];
        }

        unsigned long long c2[8][4];
#pragma unroll
        for (int i = 0; i < 8; i++)
#pragma unroll
            for (int j = 0; j < 4; j++) c2[i][j] = 0ULL;

        for (int kc = 0; kc < D_ / 16; kc++) {
            const int k0 = kc * 16;
            __syncthreads();  // consumers of previous tile done (also covers shV/shPh first iter)
            // ---- load A tile: 128 rows x 16 k, transposed+duplicated ----
#pragma unroll
            for (int h = 0; h < 2; h++) {
                int g = tid + h * 256;
                int kg = g & 3;          // float4 index along k
                int m = g >> 2;          // token row within tile
                float4 v = *(const float4*)(feat + (size_t)(bt0 + m) * D_ + k0 + kg * 4);
                *(float2*)&As2[kg * 4 + 0][2 * m] = make_float2(v.x, v.x);
                *(float2*)&As2[kg * 4 + 1][2 * m] = make_float2(v.y, v.y);
                *(float2*)&As2[kg * 4 + 2][2 * m] = make_float2(v.z, v.z);
                *(float2*)&As2[kg * 4 + 3][2 * m] = make_float2(v.w, v.w);
            }
            // ---- load B tile: 16 k x 128 n, plain ----
#pragma unroll
            for (int h = 0; h < 2; h++) {
                int g = tid + h * 256;
                int n4 = g & 31;
                int k = g >> 5;          // 0..7 then 8..15
                float4 w = *(const float4*)(W1 + (size_t)(k0 + k) * U_ + n0 + n4 * 4);
                *(float4*)&Bs[k][n4 * 4] = w;
            }
            __syncthreads();
            // ---- compute: 16 k-steps of 8x8 f32x2 outer product ----
#pragma unroll
            for (int k = 0; k < 16; k++) {
                unsigned long long a2[8], b2[4];
                const ulonglong2* ap = (const ulonglong2*)(&As2[k][r0 * 2]);
                ulonglong2 aa = ap[0], ab = ap[1], ac = ap[2], ad = ap[3];
                a2[0] = aa.x; a2[1] = aa.y; a2[2] = ab.x; a2[3] = ab.y;
                a2[4] = ac.x; a2[5] = ac.y; a2[6] = ad.x; a2[7] = ad.y;
                const ulonglong2* bp = (const ulonglong2*)(&Bs[k][c0]);
                ulonglong2 b0 = bp[0], b1 = bp[1];
                b2[0] = b0.x; b2[1] = b0.y; b2[2] = b1.x; b2[3] = b1.y;
#pragma unroll
                for (int i = 0; i < 8; i++)
#pragma unroll
                    for (int j = 0; j < 4; j++)
                        c2[i][j] = f2fma(a2[i], b2[j], c2[i][j]);
            }
        }
        // ---- epilogue: tanh + dot with V, accumulate per-row logit partials ----
#pragma unroll
        for (int i = 0; i < 8; i++) {
#pragma unroll
            for (int j = 0; j < 4; j++) {
                float2 v = unpack2(c2[i][j]);
                int c = c0 + 2 * j;
                logit[i] += tanhf(v.x + shPh[c]) * shV[c];
                logit[i] += tanhf(v.y + shPh[c + 1]) * shV[c + 1];
            }
        }
    }

    // ---- reduce logit partials across the 16 column-group threads ----
    __syncthreads();
#pragma unroll
    for (int i = 0; i < 8; i++) red[r0 + i][tx] = logit[i];
    __syncthreads();
    if (tid < 128) {
        float s = Vb[0];
#pragma unroll
        for (int x = 0; x < 16; x++) s += red[tid][x];
        g_logits[bt0 + tid] = s;
    }
}

// ---------------------------------------------------------------------------
// Kernel 3: softmax over T per batch + attention output + context vector
// grid (B, D/128), 128 threads. Softmax recomputed per d-split (cheap).
// ---------------------------------------------------------------------------
__global__ void softmax_ctx_kernel(const float* __restrict__ feat,
                                   float* __restrict__ out) {
    __shared__ float ws[T_];
    __shared__ float rbuf[128];
    const int b = blockIdx.x;
    const int ds = blockIdx.y;
    const int tid = threadIdx.x;

    float l[8];
    float mx = -1e30f;
#pragma unroll
    for (int i = 0; i < 8; i++) {
        l[i] = g_logits[b * T_ + tid * 8 + i];
        mx = fmaxf(mx, l[i]);
    }
    rbuf[tid] = mx;
    __syncthreads();
    for (int s = 64; s > 0; s >>= 1) {
        if (tid < s) rbuf[tid] = fmaxf(rbuf[tid], rbuf[tid + s]);
        __syncthreads();
    }
    mx = rbuf[0];
    __syncthreads();

    float ssum = 0.f;
#pragma unroll
    for (int i = 0; i < 8; i++) {
        l[i] = expf(l[i] - mx);
        ssum += l[i];
    }
    rbuf[tid] = ssum;
    __syncthreads();
    for (int s = 64; s > 0; s >>= 1) {
        if (tid < s) rbuf[tid] += rbuf[tid + s];
        __syncthreads();
    }
    const float inv = 1.0f / rbuf[0];
#pragma unroll
    for (int i = 0; i < 8; i++) ws[tid * 8 + i] = l[i] * inv;
    __syncthreads();

    if (ds == 0) {
        float* attn = out + B_ * D_;  // output layout: [context (B*D) | weights (B*T)]
#pragma unroll
        for (int i = 0; i < 8; i++) attn[b * T_ + tid * 8 + i] = ws[tid * 8 + i];
    }

    const int d = ds * 128 + tid;
    const float* fb = feat + (size_t)b * T_ * D_ + d;
    float acc = 0.f;
#pragma unroll 4
    for (int t = 0; t < T_; t++) acc += ws[t] * fb[(size_t)t * D_];
    out[b * D_ + d] = acc;
}

// ---------------------------------------------------------------------------
extern "C" void kernel_launch(void* const* d_in, const int* in_sizes, int n_in,
                              void* d_out, int out_size) {
    const float* feat   = (const float*)d_in[0];  // [B,T,D]
    const float* hidden = (const float*)d_in[1];  // [B,D]
    const float* W1w    = (const float*)d_in[2];  // [D,U]
    const float* W1b    = (const float*)d_in[3];  // [U]
    const float* W2w    = (const float*)d_in[4];  // [D,U]
    const float* W2b    = (const float*)d_in[5];  // [U]
    const float* Vw     = (const float*)d_in[6];  // [U,1]
    const float* Vb     = (const float*)d_in[7];  // [1]
    float* out = (float*)d_out;

    projh_kernel<<<dim3(B_, U_ / 128), 128>>>(hidden, W2w, W2b);
    score_kernel<<<(B_ * T_) / 128, 256>>>(feat, W1w, W1b, Vw, Vb);
    softmax_ctx_kernel<<<dim3(B_, D_ / 128), 128>>>(feat, out);
}

// round 4
// speedup vs baseline: 2.4710x; 2.4710x over previous
#include <cuda_runtime.h>
#include <cuda_bf16.h>
#include <math.h>

#define B_ 64
#define T_ 1024
#define D_ 512
#define U_ 1024
#define BT (B_ * T_)

// ---------------- device scratch (no allocation allowed) ----------------
__device__ __align__(128) __nv_bfloat16 g_fhi[BT * D_];     // 64 MB
__device__ __align__(128) __nv_bfloat16 g_flo[BT * D_];     // 64 MB
__device__ __align__(128) __nv_bfloat16 g_w1t_hi[U_ * D_];  // [n][k], 1 MB
__device__ __align__(128) __nv_bfloat16 g_w1t_lo[U_ * D_];
__device__ float g_projh[B_ * U_];
__device__ float g_lpart[4][BT];   // per-n-quarter logit partials

// ---------------- PTX helpers ----------------
__device__ __forceinline__ unsigned smem_u32(const void* p) {
    unsigned a;
    asm("{ .reg .u64 t; cvta.to.shared.u64 t, %1; cvt.u32.u64 %0, t; }"
        : "=r"(a) : "l"(p));
    return a;
}
__device__ __forceinline__ void cpa16(unsigned dst, const void* src) {
    asm volatile("cp.async.cg.shared.global [%0], [%1], 16;" :: "r"(dst), "l"(src));
}
__device__ __forceinline__ void cpa_commit() { asm volatile("cp.async.commit_group;"); }
__device__ __forceinline__ void ldsm4(unsigned addr, unsigned& r0, unsigned& r1,
                                      unsigned& r2, unsigned& r3) {
    asm volatile("ldmatrix.sync.aligned.m8n8.x4.shared.b16 {%0,%1,%2,%3}, [%4];"
                 : "=r"(r0), "=r"(r1), "=r"(r2), "=r"(r3) : "r"(addr));
}
__device__ __forceinline__ void mma16816(float* c, unsigned a0, unsigned a1,
                                         unsigned a2, unsigned a3,
                                         unsigned b0, unsigned b1) {
    asm volatile(
        "mma.sync.aligned.m16n8k16.row.col.f32.bf16.bf16.f32 "
        "{%0,%1,%2,%3}, {%4,%5,%6,%7}, {%8,%9}, {%0,%1,%2,%3};"
        : "+f"(c[0]), "+f"(c[1]), "+f"(c[2]), "+f"(c[3])
        : "r"(a0), "r"(a1), "r"(a2), "r"(a3), "r"(b0), "r"(b1));
}

// ---------------- smem layout for score kernel ----------------
#define STAGE 49152            // A (128x64 bf16 = 16KB) + B (256x64 bf16 = 32KB)
#define OFF_BT 16384           // B offset within stage
#define OFF_PH 196608          // 256 floats
#define OFF_V  197632          // 256 floats
#define OFF_RED 198656         // 128 x 4 floats
#define SMEM_TOTAL 200704

// ---------------------------------------------------------------------------
// split feat fp32 -> bf16 hi/lo
// ---------------------------------------------------------------------------
__global__ void fsplit_kernel(const float* __restrict__ feat) {
    long i = (long)blockIdx.x * 256 + threadIdx.x;   // one float4 per thread
    float4 v = ((const float4*)feat)[i];
    __nv_bfloat16 ha = __float2bfloat16(v.x), hb = __float2bfloat16(v.y);
    __nv_bfloat16 hc = __float2bfloat16(v.z), hd = __float2bfloat16(v.w);
    float la = v.x - __bfloat162float(ha), lb = v.y - __bfloat162float(hb);
    float lc = v.z - __bfloat162float(hc), ld = v.w - __bfloat162float(hd);
    uint2 hw, lw;
    hw.x = (unsigned)__bfloat16_as_ushort(ha) | ((unsigned)__bfloat16_as_ushort(hb) << 16);
    hw.y = (unsigned)__bfloat16_as_ushort(hc) | ((unsigned)__bfloat16_as_ushort(hd) << 16);
    lw.x = (unsigned)__bfloat16_as_ushort(__float2bfloat16(la)) |
           ((unsigned)__bfloat16_as_ushort(__float2bfloat16(lb)) << 16);
    lw.y = (unsigned)__bfloat16_as_ushort(__float2bfloat16(lc)) |
           ((unsigned)__bfloat16_as_ushort(__float2bfloat16(ld)) << 16);
    ((uint2*)g_fhi)[i] = hw;
    ((uint2*)g_flo)[i] = lw;
}

// ---------------------------------------------------------------------------
// transpose + split W1 [D,U] -> g_w1t_{hi,lo} [U][D]
// ---------------------------------------------------------------------------
__global__ void w1split_kernel(const float* __restrict__ W1) {
    __shared__ float tile[32][33];
    const int n0 = blockIdx.x * 32, k0 = blockIdx.y * 32;
    const int tx = threadIdx.x;
    for (int r = threadIdx.y; r < 32; r += 8)
        tile[r][tx] = W1[(size_t)(k0 + r) * U_ + n0 + tx];
    __syncthreads();
    for (int rr = threadIdx.y; rr < 32; rr += 8) {
        float v = tile[tx][rr];                   // W1[k0+tx][n0+rr]
        __nv_bfloat16 h = __float2bfloat16(v);
        size_t o = (size_t)(n0 + rr) * D_ + k0 + tx;
        g_w1t_hi[o] = h;
        g_w1t_lo[o] = __float2bfloat16(v - __bfloat162float(h));
    }
}

// ---------------------------------------------------------------------------
// proj_h[b,u] = hidden[b,:] @ W2[:,u] + W2_b[u];  grid (U/128, B/8), 128 thr
// ---------------------------------------------------------------------------
__global__ void projh_kernel(const float* __restrict__ hidden,
                             const float* __restrict__ W2,
                             const float* __restrict__ W2b) {
    __shared__ __align__(16) float hs[8][D_];
    const int tid = threadIdx.x;
    const int u = blockIdx.x * 128 + tid;
    const int b0 = blockIdx.y * 8;
#pragma unroll
    for (int i = 0; i < 8; i++)
        ((float4*)hs)[tid + i * 128] = ((const float4*)(hidden + (size_t)b0 * D_))[tid + i * 128];
    __syncthreads();
    float acc[8];
#pragma unroll
    for (int i = 0; i < 8; i++) acc[i] = 0.f;
#pragma unroll 4
    for (int k = 0; k < D_; k++) {
        float w = W2[(size_t)k * U_ + u];
#pragma unroll
        for (int bb = 0; bb < 8; bb++) acc[bb] += hs[bb][k] * w;
    }
    float bias = W2b[u];
#pragma unroll
    for (int bb = 0; bb < 8; bb++) g_projh[(size_t)(b0 + bb) * U_ + u] = acc[bb] + bias;
}

// ---------------------------------------------------------------------------
// score kernel: mma.sync bf16 (3-term split) GEMM + tanh + V-dot epilogue
// CTA tile 128(M) x 256(N), K chunks of 64, virtual K = 3*512 = 1536 (24 chunks)
// grid (4 n-quarters, BT/128), 256 threads (8 warps, 64x64 warp tiles)
// ---------------------------------------------------------------------------
__device__ __forceinline__ void load_chunk(unsigned sbase, int s, int c,
                                           int bt0, int n0, int tid) {
    const int seg = c >> 3;
    const int k0 = (c & 7) * 64;
    const __nv_bfloat16* Asrc = (seg == 1) ? g_flo : g_fhi;
    const __nv_bfloat16* Bsrc = (seg == 2) ? g_w1t_lo : g_w1t_hi;
    const unsigned stg = sbase + s * STAGE;
#pragma unroll
    for (int i = 0; i < 4; i++) {            // A: 128 rows x 64 k (16B granules)
        int o = tid + i * 256;
        int row = o >> 3, c16 = o & 7;
        const void* src = Asrc + (size_t)(bt0 + row) * D_ + k0 + c16 * 8;
        cpa16(stg + row * 128 + ((c16 ^ (row & 7)) * 16), src);
    }
#pragma unroll
    for (int i = 0; i < 8; i++) {            // B: 256 rows x 64 k
        int o = tid + i * 256;
        int row = o >> 3, c16 = o & 7;
        const void* src = Bsrc + (size_t)(n0 + row) * D_ + k0 + c16 * 8;
        cpa16(stg + OFF_BT + row * 128 + ((c16 ^ (row & 7)) * 16), src);
    }
}

__global__ void __launch_bounds__(256)
score_kernel(const float* __restrict__ W1b, const float* __restrict__ Vw) {
    extern __shared__ __align__(1024) char smem[];
    const unsigned sbase = smem_u32(smem);
    const int tid = threadIdx.x;
    const int wid = tid >> 5, lid = tid & 31;
    const int wm = wid & 1, wn = wid >> 1;       // 2 x 4 warp grid
    const int nq = blockIdx.x;
    const int bt0 = blockIdx.y * 128;
    const int b = bt0 >> 10;
    const int n0 = nq * 256;
    float* shPh = (float*)(smem + OFF_PH);
    float* shV  = (float*)(smem + OFF_V);
    float (*red)[4] = (float(*)[4])(smem + OFF_RED);

    shPh[tid] = g_projh[(size_t)b * U_ + n0 + tid] + W1b[n0 + tid];
    shV[tid]  = Vw[n0 + tid];

    float Cr[4][8][4];
#pragma unroll
    for (int mt = 0; mt < 4; mt++)
#pragma unroll
        for (int nt = 0; nt < 8; nt++)
#pragma unroll
            for (int j = 0; j < 4; j++) Cr[mt][nt][j] = 0.f;

    // prologue: 3 stages in flight
    load_chunk(sbase, 0, 0, bt0, n0, tid); cpa_commit();
    load_chunk(sbase, 1, 1, bt0, n0, tid); cpa_commit();
    load_chunk(sbase, 2, 2, bt0, n0, tid); cpa_commit();

    const int lrow = lid & 15;
    const int lch  = lid >> 4;

    for (int c = 0; c < 24; c++) {
        asm volatile("cp.async.wait_group 2;" ::: "memory");
        __syncthreads();
        if (c + 3 < 24) load_chunk(sbase, (c + 3) & 3, c + 3, bt0, n0, tid);
        cpa_commit();

        const unsigned Ab = sbase + (c & 3) * STAGE;
        const unsigned Bb = Ab + OFF_BT;
#pragma unroll
        for (int kk = 0; kk < 4; kk++) {     // four k16 steps in the k64 chunk
            unsigned a[4][4];
#pragma unroll
            for (int mt = 0; mt < 4; mt++) {
                int row = wm * 64 + mt * 16 + lrow;
                int ch = kk * 2 + lch;
                ldsm4(Ab + row * 128 + ((ch ^ (row & 7)) * 16),
                      a[mt][0], a[mt][1], a[mt][2], a[mt][3]);
            }
            unsigned bf[8][2];
#pragma unroll
            for (int np = 0; np < 4; np++) { // each x4 (non-trans) = two n8 tiles
                int row = wn * 64 + np * 16 + lrow;
                int ch = kk * 2 + lch;
                unsigned t0, t1, t2, t3;
                ldsm4(Bb + row * 128 + ((ch ^ (row & 7)) * 16), t0, t1, t2, t3);
                bf[np * 2][0] = t0; bf[np * 2][1] = t2;
                bf[np * 2 + 1][0] = t1; bf[np * 2 + 1][1] = t3;
            }
#pragma unroll
            for (int mt = 0; mt < 4; mt++)
#pragma unroll
                for (int nt = 0; nt < 8; nt++)
                    mma16816(Cr[mt][nt], a[mt][0], a[mt][1], a[mt][2], a[mt][3],
                             bf[nt][0], bf[nt][1]);
        }
    }

    // ---- epilogue: tanh + V-dot on fragments ----
    float p[4][2];
#pragma unroll
    for (int mt = 0; mt < 4; mt++) { p[mt][0] = 0.f; p[mt][1] = 0.f; }
#pragma unroll
    for (int mt = 0; mt < 4; mt++)
#pragma unroll
        for (int nt = 0; nt < 8; nt++) {
            int nc = wn * 64 + nt * 8 + (lid & 3) * 2;
            float ph0 = shPh[nc], ph1 = shPh[nc + 1];
            float v0 = shV[nc], v1 = shV[nc + 1];
            p[mt][0] += tanhf(Cr[mt][nt][0] + ph0) * v0
                      + tanhf(Cr[mt][nt][1] + ph1) * v1;
            p[mt][1] += tanhf(Cr[mt][nt][2] + ph0) * v0
                      + tanhf(Cr[mt][nt][3] + ph1) * v1;
        }
#pragma unroll
    for (int mt = 0; mt < 4; mt++) {
#pragma unroll
        for (int j = 0; j < 2; j++) {
            p[mt][j] += __shfl_xor_sync(0xFFFFFFFFu, p[mt][j], 1);
            p[mt][j] += __shfl_xor_sync(0xFFFFFFFFu, p[mt][j], 2);
        }
    }
    if ((lid & 3) == 0) {
#pragma unroll
        for (int mt = 0; mt < 4; mt++) {
            int rl = wm * 64 + mt * 16 + (lid >> 2);
            red[rl][wn] = p[mt][0];
            red[rl + 8][wn] = p[mt][1];
        }
    }
    __syncthreads();
    if (tid < 128) {
        float s = red[tid][0] + red[tid][1] + red[tid][2] + red[tid][3];
        g_lpart[nq][bt0 + tid] = s;
    }
}

// ---------------------------------------------------------------------------
// softmax over T + attention weights + context vector
// ---------------------------------------------------------------------------
__global__ void softmax_ctx_kernel(const float* __restrict__ feat,
                                   const float* __restrict__ Vb,
                                   float* __restrict__ out) {
    __shared__ float ws[T_];
    __shared__ float rbuf[128];
    const int b = blockIdx.x;
    const int ds = blockIdx.y;
    const int tid = threadIdx.x;

    float l[8];
    float mx = -1e30f;
    const float vb = Vb[0];
#pragma unroll
    for (int i = 0; i < 8; i++) {
        int idx = b * T_ + tid * 8 + i;
        l[i] = g_lpart[0][idx] + g_lpart[1][idx] + g_lpart[2][idx] + g_lpart[3][idx] + vb;
        mx = fmaxf(mx, l[i]);
    }
    rbuf[tid] = mx;
    __syncthreads();
    for (int s = 64; s > 0; s >>= 1) {
        if (tid < s) rbuf[tid] = fmaxf(rbuf[tid], rbuf[tid + s]);
        __syncthreads();
    }
    mx = rbuf[0];
    __syncthreads();

    float ssum = 0.f;
#pragma unroll
    for (int i = 0; i < 8; i++) {
        l[i] = expf(l[i] - mx);
        ssum += l[i];
    }
    rbuf[tid] = ssum;
    __syncthreads();
    for (int s = 64; s > 0; s >>= 1) {
        if (tid < s) rbuf[tid] += rbuf[tid + s];
        __syncthreads();
    }
    const float inv = 1.0f / rbuf[0];
#pragma unroll
    for (int i = 0; i < 8; i++) ws[tid * 8 + i] = l[i] * inv;
    __syncthreads();

    if (ds == 0) {
        float* attn = out + B_ * D_;
#pragma unroll
        for (int i = 0; i < 8; i++) attn[b * T_ + tid * 8 + i] = ws[tid * 8 + i];
    }

    const int d = ds * 128 + tid;
    const float* fb = feat + (size_t)b * T_ * D_ + d;
    float acc = 0.f;
#pragma unroll 4
    for (int t = 0; t < T_; t++) acc += ws[t] * fb[(size_t)t * D_];
    out[b * D_ + d] = acc;
}

// ---------------------------------------------------------------------------
extern "C" void kernel_launch(void* const* d_in, const int* in_sizes, int n_in,
                              void* d_out, int out_size) {
    const float* feat   = (const float*)d_in[0];
    const float* hidden = (const float*)d_in[1];
    const float* W1w    = (const float*)d_in[2];
    const float* W1b    = (const float*)d_in[3];
    const float* W2w    = (const float*)d_in[4];
    const float* W2b    = (const float*)d_in[5];
    const float* Vw     = (const float*)d_in[6];
    const float* Vb     = (const float*)d_in[7];
    float* out = (float*)d_out;

    static bool attr_set = false;
    if (!attr_set) {
        cudaFuncSetAttribute(score_kernel, cudaFuncAttributeMaxDynamicSharedMemorySize,
                             SMEM_TOTAL);
        attr_set = true;
    }

    fsplit_kernel<<<BT * D_ / 4 / 256, 256>>>(feat);
    w1split_kernel<<<dim3(U_ / 32, D_ / 32), dim3(32, 8)>>>(W1w);
    projh_kernel<<<dim3(U_ / 128, B_ / 8), 128>>>(hidden, W2w, W2b);
    score_kernel<<<dim3(4, BT / 128), 256, SMEM_TOTAL>>>(W1b, Vw);
    softmax_ctx_kernel<<<dim3(B_, D_ / 128), 128>>>(feat, Vb, out);
}